// round 12
// baseline (speedup 1.0000x reference)
#include <cuda_runtime.h>
#include <math.h>

#define HH 512
#define WW 512
#define HWSZ (HH * WW)
#define NTHREADS 512
#define NWARPS 16
#define EPSV 1e-8f

#define MAXPLANES 256
#define STRIDE_ST 2052
#define BANDROWS 16
#define BANDS (HH / BANDROWS)
#define K2_THREADS 256
#define K2_GRID (148 * 6)

__device__ float g_stats[MAXPLANES * STRIDE_ST];
__device__ unsigned int g_counter;

__global__ __launch_bounds__(NTHREADS, 2) void stats_kernel(
    const float* __restrict__ in, int C)
{
    __shared__ __align__(16) float rowS[HH];
    __shared__ __align__(16) float rowSS[HH];
    __shared__ __align__(16) float colS[WW];
    __shared__ __align__(16) float colSS[WW];
    __shared__ float warpRed[NWARPS * 2];
    __shared__ float sIns[2];

    const int plane = blockIdx.x;
    const float* __restrict__ p = in + (size_t)plane * HWSZ;

    const int tid = threadIdx.x;
    const int lane = tid & 31;
    const int wid = tid >> 5;

    if (plane == 0 && tid == 0) g_counter = 0u;

    colS[tid] = 0.f;
    colSS[tid] = 0.f;
    __syncthreads();

    float cs[16], css[16];
#pragma unroll
    for (int i = 0; i < 16; i++) { cs[i] = 0.f; css[i] = 0.f; }

    for (int r = wid; r < HH; r += NWARPS) {
        const float4* rp = (const float4*)(p + (size_t)r * WW);
        float4 v[4];
#pragma unroll
        for (int k = 0; k < 4; k++) v[k] = __ldcg(&rp[k * 32 + lane]);

        float s = 0.f, ss = 0.f;
#pragma unroll
        for (int k = 0; k < 4; k++) {
            s += (v[k].x + v[k].y) + (v[k].z + v[k].w);
            ss += v[k].x * v[k].x + v[k].y * v[k].y + v[k].z * v[k].z + v[k].w * v[k].w;
            cs[k * 4 + 0] += v[k].x;  css[k * 4 + 0] += v[k].x * v[k].x;
            cs[k * 4 + 1] += v[k].y;  css[k * 4 + 1] += v[k].y * v[k].y;
            cs[k * 4 + 2] += v[k].z;  css[k * 4 + 2] += v[k].z * v[k].z;
            cs[k * 4 + 3] += v[k].w;  css[k * 4 + 3] += v[k].w * v[k].w;
        }
#pragma unroll
        for (int o = 16; o > 0; o >>= 1) {
            s += __shfl_xor_sync(0xffffffffu, s, o);
            ss += __shfl_xor_sync(0xffffffffu, ss, o);
        }
        if (lane == 0) { rowS[r] = s; rowSS[r] = ss; }
    }

#pragma unroll
    for (int k = 0; k < 4; k++) {
        int cbase = (k * 32 + lane) * 4;
#pragma unroll
        for (int j = 0; j < 4; j++) {
            atomicAdd(&colS[cbase + j], cs[k * 4 + j]);
            atomicAdd(&colSS[cbase + j], css[k * 4 + j]);
        }
    }
    __syncthreads();

    {
        float s = rowS[tid], ss = rowSS[tid];
#pragma unroll
        for (int o = 16; o > 0; o >>= 1) {
            s += __shfl_xor_sync(0xffffffffu, s, o);
            ss += __shfl_xor_sync(0xffffffffu, ss, o);
        }
        if (lane == 0) { warpRed[wid] = s; warpRed[NWARPS + wid] = ss; }
    }
    __syncthreads();
    if (tid == 0) {
        float s = 0.f, ss = 0.f;
        for (int i = 0; i < NWARPS; i++) { s += warpRed[i]; ss += warpRed[NWARPS + i]; }
        float m = s * (1.f / HWSZ);
        float v = fmaxf(ss * (1.f / HWSZ) - m * m, 0.f);
        sIns[0] = m;
        sIns[1] = 1.f / (sqrtf(v + EPSV) + EPSV);
    }

    float rm, ri, cm, ci;
    {
        float m = rowS[tid] * (1.f / WW);
        float v = fmaxf(rowSS[tid] * (1.f / WW) - m * m, 0.f);
        rm = m;
        ri = 1.f / (sqrtf(v + EPSV) + EPSV);

        float mc = colS[tid] * (1.f / HH);
        float vc = fmaxf(colSS[tid] * (1.f / HH) - mc * mc, 0.f);
        cm = mc;
        ci = 1.f / (sqrtf(vc + EPSV) + EPSV);
    }
    __syncthreads();

    float* st = g_stats + (size_t)plane * STRIDE_ST;
    st[tid] = rm;
    st[512 + tid] = ri;
    st[1024 + tid] = cm;
    st[1536 + tid] = ci;
    if (tid == 0) { st[2048] = sIns[0]; st[2049] = sIns[1]; }
}

__global__ __launch_bounds__(K2_THREADS, 6) void norm_kernel(
    const float* __restrict__ in,
    const float* __restrict__ gRow_p, const float* __restrict__ bRow_p,
    const float* __restrict__ gCol_p, const float* __restrict__ bCol_p,
    const float* __restrict__ gIns_p, const float* __restrict__ bIns_p,
    float* __restrict__ out, int C, int nPlanes)
{
    __shared__ __align__(16) float sColM[WW];
    __shared__ __align__(16) float sColI[WW];
    __shared__ float sRowM[BANDROWS];
    __shared__ float sRowI[BANDROWS];
    __shared__ float sP[8];
    __shared__ unsigned int sU;

    const int tid = threadIdx.x;
    const int lane = tid & 31;
    const int w = tid >> 5;
    const unsigned int nUnits = (unsigned int)(nPlanes * BANDS);

    for (;;) {
        if (tid == 0) sU = atomicAdd(&g_counter, 1u);
        __syncthreads();
        unsigned int u = sU;
        if (u >= nUnits) break;

        const int u2 = (int)(nUnits - 1u - u);
        const int plane = u2 >> 5;
        const int band = u2 & (BANDS - 1);
        const float* __restrict__ st = g_stats + (size_t)plane * STRIDE_ST;

        sColM[tid]       = st[1024 + tid];
        sColM[tid + 256] = st[1024 + 256 + tid];
        sColI[tid]       = st[1536 + tid];
        sColI[tid + 256] = st[1536 + 256 + tid];
        if (tid < BANDROWS) {
            sRowM[tid] = st[band * BANDROWS + tid];
            sRowI[tid] = st[512 + band * BANDROWS + tid];
        }
        if (tid == 0) {
            const int c = plane % C;
            sP[0] = st[2048];  sP[1] = st[2049];
            sP[2] = gRow_p[c]; sP[3] = bRow_p[c];
            sP[4] = gCol_p[c]; sP[5] = bCol_p[c];
            sP[6] = gIns_p[c]; sP[7] = bIns_p[c];
        }
        __syncthreads();

        const int c = plane % C;
        const int b = plane / C;
        const float insM = sP[0], insI = sP[1];
        const float gRow = sP[2], bRow = sP[3];
        const float gCol = sP[4], bCol = sP[5];
        const float gIns = sP[6], bIns = sP[7];

        const size_t outBase = (size_t)b * 3 * C * HWSZ;
        float* __restrict__ oI = out + outBase + (size_t)c * HWSZ;
        float* __restrict__ oR = out + outBase + (size_t)(C + c) * HWSZ;
        float* __restrict__ oC = out + outBase + (size_t)(2 * C + c) * HWSZ;
        const float* __restrict__ p = in + (size_t)plane * HWSZ;

        const float4* colM4 = (const float4*)sColM;
        const float4* colI4 = (const float4*)sColI;

#pragma unroll
        for (int j = 0; j < 2; j++) {
            const int rl = w * 2 + j;
            const int r = band * BANDROWS + rl;
            const float4* rp = (const float4*)(p + (size_t)r * WW);
            float4* oIp = (float4*)(oI + (size_t)r * WW);
            float4* oRp = (float4*)(oR + (size_t)r * WW);
            float4* oCp = (float4*)(oC + (size_t)r * WW);
            const float rm = sRowM[rl];
            const float ri = sRowI[rl];
#pragma unroll
            for (int k = 0; k < 4; k++) {
                const int idx = k * 32 + lane;
                float4 v = __ldcs(&rp[idx]);
                float4 cm = colM4[idx];
                float4 ci = colI4[idx];
                float4 o;
                o.x = gIns * (v.x - insM) * insI + bIns;
                o.y = gIns * (v.y - insM) * insI + bIns;
                o.z = gIns * (v.z - insM) * insI + bIns;
                o.w = gIns * (v.w - insM) * insI + bIns;
                __stcs(&oIp[idx], o);
                o.x = gRow * (v.x - rm) * ri + bRow;
                o.y = gRow * (v.y - rm) * ri + bRow;
                o.z = gRow * (v.z - rm) * ri + bRow;
                o.w = gRow * (v.w - rm) * ri + bRow;
                __stcs(&oRp[idx], o);
                o.x = gCol * (v.x - cm.x) * ci.x + bCol;
                o.y = gCol * (v.y - cm.y) * ci.y + bCol;
                o.z = gCol * (v.z - cm.z) * ci.z + bCol;
                o.w = gCol * (v.w - cm.w) * ci.w + bCol;
                __stcs(&oCp[idx], o);
            }
        }
    }
}

extern "C" void kernel_launch(void* const* d_in, const int* in_sizes, int n_in,
                              void* d_out, int out_size) {
    const float* in = (const float*)d_in[0];
    const float* gRow = (const float*)d_in[1];
    const float* bRow = (const float*)d_in[2];
    const float* gCol = (const float*)d_in[3];
    const float* bCol = (const float*)d_in[4];
    const float* gIns = (const float*)d_in[5];
    const float* bIns = (const float*)d_in[6];
    float* out = (float*)d_out;

    const int C = in_sizes[1];                  // 128
    const int nPlanes = in_sizes[0] / HWSZ;     // B*C = 256

    stats_kernel<<<nPlanes, NTHREADS>>>(in, C);
    norm_kernel<<<K2_GRID, K2_THREADS>>>(in, gRow, bRow, gCol, bCol,
                                         gIns, bIns, out, C, nPlanes);
}